// round 3
// baseline (speedup 1.0000x reference)
#include <cuda_runtime.h>
#include <cstdint>

// CharRNN on GB300 (sm_103a), round 3.
// 128 blocks x 384 threads (12 warps), block owns 8 batch rows.
// Layers 0..7: one full warp each (lane owns 2 neurons x 4 rows, 256 ffma2/step).
// Layers 8,9: two half-warps each (rows split 4/4, lane owns 1 neuron, 128 ffma2/step).
// Warp->SMSP mapping gives every SMSP exactly Full+Full+Half = 640 ffma2-issues/step.
// 4 timesteps per tick, depth-8 shared ring per layer, pairwise named barriers.
// Embeddings prefetched 40 steps ahead by the half-warps into a depth-80 ring;
// correctness rides the transitive per-tick barrier chain (9 hops L9<->L0).

#define NBLK  128
#define NTHR  384
#define ROWS  8
#define TT    1024
#define LL    10
#define HID   32
#define VOC   256
#define LST   36              // padded row stride (floats), 16B aligned
#define RL    (ROWS*LST)      // floats per ring slot (288)
#define DEPTH 8               // layer ring depth (steps)
#define XDEP  80              // embedding ring depth (steps)
#define PREF  40              // embedding prefetch distance (steps)
#define NTICK 265             // 1024/4 + 9

typedef unsigned long long ull;

__device__ __forceinline__ void ffma2(ull &d, ull a, ull b) {
    asm("fma.rn.f32x2 %0, %1, %2, %0;" : "+l"(d) : "l"(a), "l"(b));
}
__device__ __forceinline__ float f2red(ull a) {
    float lo, hi;
    asm("mov.b64 {%0, %1}, %2;" : "=f"(lo), "=f"(hi) : "l"(a));
    return lo + hi;
}
__device__ __forceinline__ float tanh_fast(float x) {
    float e = __expf(2.0f * x);
    return 1.0f - __fdividef(2.0f, e + 1.0f);
}
__device__ __forceinline__ void nbar(int id, int cnt) {
    asm volatile("bar.sync %0, %1;" :: "r"(id), "r"(cnt) : "memory");
}

__global__ void __launch_bounds__(NTHR, 1)
charrnn_kernel(const int*   __restrict__ x,      // [B, T]
               const float* __restrict__ emb,    // [VOC, 32]
               const float* __restrict__ W_ih,   // [L, 32, 32]
               const float* __restrict__ W_hh,   // [L, 32, 32]
               const float* __restrict__ b_ih,   // [L, 32]
               const float* __restrict__ b_hh,   // [L, 32]
               const float* __restrict__ W_fc,   // [VOC, 32]
               const float* __restrict__ b_fc,   // [VOC]
               float*       __restrict__ out)    // [B, VOC]
{
    extern __shared__ float smem[];
    float* shl = smem;                    // [LL][DEPTH][ROWS][LST]
    float* sx  = smem + LL * DEPTH * RL;  // [XDEP][ROWS][LST]

    const int tid  = threadIdx.x;
    const int wid  = tid >> 5;
    const int lane = tid & 31;
    const int row0 = blockIdx.x * ROWS;

    // zero layer rings (h(-1)=0 lives in slot DEPTH-1)
    for (int i = tid; i < LL * DEPTH * RL; i += NTHR) shl[i] = 0.0f;

    const bool isFull = (wid < 8);

    // =========================== FULL WARP ===========================
    if (isFull) {
        const int l    = wid;           // layer 0..7
        const int half = lane >> 4;
        const int n0   = lane & 15;
        const int n1   = n0 + 16;

        ull wih0[16], wih1[16], whh0[16], whh1[16];
        {
            const ulonglong2* p;
            p = (const ulonglong2*)(W_ih + (l * HID + n0) * HID);
            #pragma unroll
            for (int q = 0; q < 8; ++q) { ulonglong2 v = p[q]; wih0[2*q] = v.x; wih0[2*q+1] = v.y; }
            p = (const ulonglong2*)(W_ih + (l * HID + n1) * HID);
            #pragma unroll
            for (int q = 0; q < 8; ++q) { ulonglong2 v = p[q]; wih1[2*q] = v.x; wih1[2*q+1] = v.y; }
            p = (const ulonglong2*)(W_hh + (l * HID + n0) * HID);
            #pragma unroll
            for (int q = 0; q < 8; ++q) { ulonglong2 v = p[q]; whh0[2*q] = v.x; whh0[2*q+1] = v.y; }
            p = (const ulonglong2*)(W_hh + (l * HID + n1) * HID);
            #pragma unroll
            for (int q = 0; q < 8; ++q) { ulonglong2 v = p[q]; whh1[2*q] = v.x; whh1[2*q+1] = v.y; }
        }
        const float bias0 = __ldg(&b_ih[l * HID + n0]) + __ldg(&b_hh[l * HID + n0]);
        const float bias1 = __ldg(&b_ih[l * HID + n1]) + __ldg(&b_hh[l * HID + n1]);

        // prefill help: warps 0..7 fill part of sx steps [0, PREF)
        for (int i = wid; i < PREF * ROWS; i += 12) {
            const int t = i >> 3, r = i & 7;
            const int idx = __ldg(&x[(row0 + r) * TT + t]);
            sx[t * RL + r * LST + lane] = __ldg(&emb[idx * HID + lane]);
        }
        __syncthreads();

        const float* base_in  = (l == 0) ? sx : (shl + (l - 1) * DEPTH * RL);
        float*       base_own = shl + l * DEPTH * RL;
        const int    up_cnt   = 64;
        const int    dn_cnt   = (l == 7) ? 96 : 64;
        int xs = 0;  // sx read cursor (layer 0 only)

        for (int v = 0; v < NTICK; ++v) {
            const int t0 = 4 * (v - l);
            if (t0 >= 0 && t0 < TT) {
                #pragma unroll
                for (int st = 0; st < 4; ++st) {
                    const int t = t0 + st;
                    const float* inb = (l == 0) ? (sx + (xs + st) * RL)
                                                : (base_in + (t & (DEPTH-1)) * RL);
                    const float* hb  = base_own + ((t - 1) & (DEPTH-1)) * RL;
                    float*       ob  = base_own + (t & (DEPTH-1)) * RL;

                    ull acc0[4], acc1[4];
                    #pragma unroll
                    for (int r = 0; r < 4; ++r) { acc0[r] = 0ull; acc1[r] = 0ull; }
                    #pragma unroll
                    for (int r = 0; r < 4; ++r) {
                        const int rr = half * 4 + r;
                        #pragma unroll
                        for (int q = 0; q < 8; ++q) {
                            ulonglong2 va = *(const ulonglong2*)(inb + rr * LST + q * 4);
                            ffma2(acc0[r], wih0[2*q], va.x); ffma2(acc0[r], wih0[2*q+1], va.y);
                            ffma2(acc1[r], wih1[2*q], va.x); ffma2(acc1[r], wih1[2*q+1], va.y);
                        }
                        #pragma unroll
                        for (int q = 0; q < 8; ++q) {
                            ulonglong2 vh = *(const ulonglong2*)(hb + rr * LST + q * 4);
                            ffma2(acc0[r], whh0[2*q], vh.x); ffma2(acc0[r], whh0[2*q+1], vh.y);
                            ffma2(acc1[r], whh1[2*q], vh.x); ffma2(acc1[r], whh1[2*q+1], vh.y);
                        }
                    }
                    #pragma unroll
                    for (int r = 0; r < 4; ++r) {
                        const int rr = half * 4 + r;
                        ob[rr * LST + n0] = tanh_fast(f2red(acc0[r]) + bias0);
                        ob[rr * LST + n1] = tanh_fast(f2red(acc1[r]) + bias1);
                    }
                    __syncwarp();
                }
                if (l == 0) { xs += 4; if (xs == XDEP) xs = 0; }
            }
            if (l >= 1) nbar(l + 1, up_cnt);
            nbar(l + 2, dn_cnt);
        }
    }
    // =========================== HALF WARP ===========================
    else {
        const int hw = wid - 8;           // 0..3
        const int lh = 8 + (hw >> 1);     // layer 8 or 9
        const int rb = (hw & 1) * 4;      // row base (0 or 4)
        const int r0e = 2 * hw;           // embedding rows owned
        const int r1e = 2 * hw + 1;

        ull wih[16], whh[16];
        {
            const ulonglong2* p;
            p = (const ulonglong2*)(W_ih + (lh * HID + lane) * HID);
            #pragma unroll
            for (int q = 0; q < 8; ++q) { ulonglong2 v = p[q]; wih[2*q] = v.x; wih[2*q+1] = v.y; }
            p = (const ulonglong2*)(W_hh + (lh * HID + lane) * HID);
            #pragma unroll
            for (int q = 0; q < 8; ++q) { ulonglong2 v = p[q]; whh[2*q] = v.x; whh[2*q+1] = v.y; }
        }
        const float bias = __ldg(&b_ih[lh * HID + lane]) + __ldg(&b_hh[lh * HID + lane]);

        for (int i = wid; i < PREF * ROWS; i += 12) {
            const int t = i >> 3, r = i & 7;
            const int idx = __ldg(&x[(row0 + r) * TT + t]);
            sx[t * RL + r * LST + lane] = __ldg(&emb[idx * HID + lane]);
        }
        __syncthreads();

        const float* base_in  = shl + (lh - 1) * DEPTH * RL;
        float*       base_own = shl + lh * DEPTH * RL;

        // embedding index preload for first tick (t = PREF)
        int4 xiA = *(const int4*)(x + (row0 + r0e) * TT + PREF);
        int4 xiB = *(const int4*)(x + (row0 + r1e) * TT + PREF);
        int ws = PREF;  // sx write cursor

        for (int v = 0; v < NTICK; ++v) {
            // ---- embedding gather (40 steps ahead of layer 0) ----
            const int te = 4 * v + PREF;
            const bool doemb = (te < TT);
            float g[8];
            if (doemb) {
                g[0] = __ldg(&emb[xiA.x * HID + lane]);
                g[1] = __ldg(&emb[xiA.y * HID + lane]);
                g[2] = __ldg(&emb[xiA.z * HID + lane]);
                g[3] = __ldg(&emb[xiA.w * HID + lane]);
                g[4] = __ldg(&emb[xiB.x * HID + lane]);
                g[5] = __ldg(&emb[xiB.y * HID + lane]);
                g[6] = __ldg(&emb[xiB.z * HID + lane]);
                g[7] = __ldg(&emb[xiB.w * HID + lane]);
                const int tn = te + 4;
                if (tn < TT) {
                    xiA = *(const int4*)(x + (row0 + r0e) * TT + tn);
                    xiB = *(const int4*)(x + (row0 + r1e) * TT + tn);
                }
            }

            // ---- RNN: 4 steps for own 4 rows ----
            const int t0 = 4 * (v - lh);
            if (t0 >= 0 && t0 < TT) {
                #pragma unroll
                for (int st = 0; st < 4; ++st) {
                    const int t = t0 + st;
                    const float* inb = base_in  + (t & (DEPTH-1)) * RL;
                    const float* hb  = base_own + ((t - 1) & (DEPTH-1)) * RL;
                    float*       ob  = base_own + (t & (DEPTH-1)) * RL;

                    ull acc[4];
                    #pragma unroll
                    for (int r = 0; r < 4; ++r) acc[r] = 0ull;
                    #pragma unroll
                    for (int r = 0; r < 4; ++r) {
                        const int rr = rb + r;
                        #pragma unroll
                        for (int q = 0; q < 8; ++q) {
                            ulonglong2 va = *(const ulonglong2*)(inb + rr * LST + q * 4);
                            ffma2(acc[r], wih[2*q], va.x); ffma2(acc[r], wih[2*q+1], va.y);
                        }
                        #pragma unroll
                        for (int q = 0; q < 8; ++q) {
                            ulonglong2 vh = *(const ulonglong2*)(hb + rr * LST + q * 4);
                            ffma2(acc[r], whh[2*q], vh.x); ffma2(acc[r], whh[2*q+1], vh.y);
                        }
                    }
                    #pragma unroll
                    for (int r = 0; r < 4; ++r)
                        ob[(rb + r) * LST + lane] = tanh_fast(f2red(acc[r]) + bias);
                    __syncwarp();
                }
            }

            // ---- store gathered embeddings ----
            if (doemb) {
                #pragma unroll
                for (int s = 0; s < 4; ++s) {
                    sx[(ws + s) * RL + r0e * LST + lane] = g[s];
                    sx[(ws + s) * RL + r1e * LST + lane] = g[4 + s];
                }
                ws += 4; if (ws == XDEP) ws = 0;
            }

            if (lh == 8) { nbar(9, 96); nbar(10, 128); }
            else         { nbar(10, 128); }
        }
    }

    __syncthreads();

    // ---- final FC: out = h9(1023) @ W_fc^T + b_fc ; slot 1023&7 = 7 ----
    const float* h9 = shl + ((LL - 1) * DEPTH + 7) * RL;
    for (int i = tid; i < ROWS * VOC; i += NTHR) {
        const int r = i >> 8;
        const int v = i & (VOC - 1);
        const float4* w  = (const float4*)(W_fc + v * HID);
        const float*  hr = h9 + r * LST;
        float sum = __ldg(&b_fc[v]);
        #pragma unroll
        for (int q = 0; q < 8; ++q) {
            float4 a = w[q];
            sum += a.x * hr[q*4+0] + a.y * hr[q*4+1] + a.z * hr[q*4+2] + a.w * hr[q*4+3];
        }
        out[(row0 + r) * VOC + v] = sum;
    }
}

extern "C" void kernel_launch(void* const* d_in, const int* in_sizes, int n_in,
                              void* d_out, int out_size)
{
    const int*   x    = (const int*)  d_in[0];
    const float* emb  = (const float*)d_in[1];
    const float* W_ih = (const float*)d_in[2];
    const float* W_hh = (const float*)d_in[3];
    const float* b_ih = (const float*)d_in[4];
    const float* b_hh = (const float*)d_in[5];
    const float* W_fc = (const float*)d_in[6];
    const float* b_fc = (const float*)d_in[7];
    float* out = (float*)d_out;

    const int shbytes = (LL * DEPTH + XDEP) * RL * (int)sizeof(float);  // 184320
    cudaFuncSetAttribute(charrnn_kernel,
                         cudaFuncAttributeMaxDynamicSharedMemorySize, shbytes);
    charrnn_kernel<<<NBLK, NTHR, shbytes>>>(x, emb, W_ih, W_hh, b_ih, b_hh,
                                            W_fc, b_fc, out);
}

// round 4
// speedup vs baseline: 1.0009x; 1.0009x over previous
#include <cuda_runtime.h>
#include <cstdint>

// CharRNN on GB300 (sm_103a), round 4.
// Structure identical to round 3 (128 blocks x 384 thr, 8 full-layer warps +
// 4 half-layer warps, 4 steps/tick, named pairwise barriers, embedding ring),
// plus software pipelining of the step recurrence: the wih.x(t+1) partial sums
// (independent of h(t)) are issued BEFORE the __syncwarp that publishes h(t),
// so the post-sync critical path is only LDS + whh chain + tanh.

#define NBLK  128
#define NTHR  384
#define ROWS  8
#define TT    1024
#define LL    10
#define HID   32
#define VOC   256
#define LST   36
#define RL    (ROWS*LST)
#define DEPTH 8
#define XDEP  80
#define PREF  40
#define NTICK 265

typedef unsigned long long ull;

__device__ __forceinline__ void ffma2(ull &d, ull a, ull b) {
    asm("fma.rn.f32x2 %0, %1, %2, %0;" : "+l"(d) : "l"(a), "l"(b));
}
__device__ __forceinline__ float f2red(ull a) {
    float lo, hi;
    asm("mov.b64 {%0, %1}, %2;" : "=f"(lo), "=f"(hi) : "l"(a));
    return lo + hi;
}
__device__ __forceinline__ float tanh_fast(float x) {
    float e = __expf(2.0f * x);
    return 1.0f - __fdividef(2.0f, e + 1.0f);
}
__device__ __forceinline__ void nbar(int id, int cnt) {
    asm volatile("bar.sync %0, %1;" :: "r"(id), "r"(cnt) : "memory");
}

__global__ void __launch_bounds__(NTHR, 1)
charrnn_kernel(const int*   __restrict__ x,
               const float* __restrict__ emb,
               const float* __restrict__ W_ih,
               const float* __restrict__ W_hh,
               const float* __restrict__ b_ih,
               const float* __restrict__ b_hh,
               const float* __restrict__ W_fc,
               const float* __restrict__ b_fc,
               float*       __restrict__ out)
{
    extern __shared__ float smem[];
    float* shl = smem;                    // [LL][DEPTH][ROWS][LST]
    float* sx  = smem + LL * DEPTH * RL;  // [XDEP][ROWS][LST]

    const int tid  = threadIdx.x;
    const int wid  = tid >> 5;
    const int lane = tid & 31;
    const int row0 = blockIdx.x * ROWS;

    for (int i = tid; i < LL * DEPTH * RL; i += NTHR) shl[i] = 0.0f;

    const bool isFull = (wid < 8);

    // =========================== FULL WARP ===========================
    if (isFull) {
        const int l    = wid;
        const int half = lane >> 4;
        const int n0   = lane & 15;
        const int n1   = n0 + 16;

        ull wih0[16], wih1[16], whh0[16], whh1[16];
        {
            const ulonglong2* p;
            p = (const ulonglong2*)(W_ih + (l * HID + n0) * HID);
            #pragma unroll
            for (int q = 0; q < 8; ++q) { ulonglong2 v = p[q]; wih0[2*q] = v.x; wih0[2*q+1] = v.y; }
            p = (const ulonglong2*)(W_ih + (l * HID + n1) * HID);
            #pragma unroll
            for (int q = 0; q < 8; ++q) { ulonglong2 v = p[q]; wih1[2*q] = v.x; wih1[2*q+1] = v.y; }
            p = (const ulonglong2*)(W_hh + (l * HID + n0) * HID);
            #pragma unroll
            for (int q = 0; q < 8; ++q) { ulonglong2 v = p[q]; whh0[2*q] = v.x; whh0[2*q+1] = v.y; }
            p = (const ulonglong2*)(W_hh + (l * HID + n1) * HID);
            #pragma unroll
            for (int q = 0; q < 8; ++q) { ulonglong2 v = p[q]; whh1[2*q] = v.x; whh1[2*q+1] = v.y; }
        }
        const float bias0 = __ldg(&b_ih[l * HID + n0]) + __ldg(&b_hh[l * HID + n0]);
        const float bias1 = __ldg(&b_ih[l * HID + n1]) + __ldg(&b_hh[l * HID + n1]);

        for (int i = wid; i < PREF * ROWS; i += 12) {
            const int t = i >> 3, r = i & 7;
            const int idx = __ldg(&x[(row0 + r) * TT + t]);
            sx[t * RL + r * LST + lane] = __ldg(&emb[idx * HID + lane]);
        }
        __syncthreads();

        const float* base_in  = (l == 0) ? sx : (shl + (l - 1) * DEPTH * RL);
        float*       base_own = shl + l * DEPTH * RL;
        const int    up_cnt   = 64;
        const int    dn_cnt   = (l == 7) ? 96 : 64;
        int xs = 0;

        ull acc0[4], acc1[4];

        for (int v = 0; v < NTICK; ++v) {
            const int t0 = 4 * (v - l);
            if (t0 >= 0 && t0 < TT) {
                // ---- wih-part for st = 0 (inputs ready since last tick bar) ----
                {
                    const float* inb = (l == 0) ? (sx + xs * RL)
                                                : (base_in + (t0 & (DEPTH-1)) * RL);
                    #pragma unroll
                    for (int r = 0; r < 4; ++r) { acc0[r] = 0ull; acc1[r] = 0ull; }
                    #pragma unroll
                    for (int r = 0; r < 4; ++r) {
                        const int rr = half * 4 + r;
                        #pragma unroll
                        for (int q = 0; q < 8; ++q) {
                            ulonglong2 va = *(const ulonglong2*)(inb + rr * LST + q * 4);
                            ffma2(acc0[r], wih0[2*q], va.x); ffma2(acc0[r], wih0[2*q+1], va.y);
                            ffma2(acc1[r], wih1[2*q], va.x); ffma2(acc1[r], wih1[2*q+1], va.y);
                        }
                    }
                }
                #pragma unroll
                for (int st = 0; st < 4; ++st) {
                    const int t = t0 + st;
                    __syncwarp();   // publish h(t-1) (tick bar covers st=0)
                    const float* hb = base_own + ((t - 1) & (DEPTH-1)) * RL;
                    float*       ob = base_own + (t & (DEPTH-1)) * RL;

                    // ---- whh-part (the true recurrence) ----
                    #pragma unroll
                    for (int r = 0; r < 4; ++r) {
                        const int rr = half * 4 + r;
                        #pragma unroll
                        for (int q = 0; q < 8; ++q) {
                            ulonglong2 vh = *(const ulonglong2*)(hb + rr * LST + q * 4);
                            ffma2(acc0[r], whh0[2*q], vh.x); ffma2(acc0[r], whh0[2*q+1], vh.y);
                            ffma2(acc1[r], whh1[2*q], vh.x); ffma2(acc1[r], whh1[2*q+1], vh.y);
                        }
                    }
                    #pragma unroll
                    for (int r = 0; r < 4; ++r) {
                        const int rr = half * 4 + r;
                        ob[rr * LST + n0] = tanh_fast(f2red(acc0[r]) + bias0);
                        ob[rr * LST + n1] = tanh_fast(f2red(acc1[r]) + bias1);
                    }

                    // ---- hoisted wih-part for t+1 (independent of h(t)) ----
                    if (st < 3) {
                        const float* inb = (l == 0) ? (sx + (xs + st + 1) * RL)
                                                    : (base_in + ((t + 1) & (DEPTH-1)) * RL);
                        #pragma unroll
                        for (int r = 0; r < 4; ++r) { acc0[r] = 0ull; acc1[r] = 0ull; }
                        #pragma unroll
                        for (int r = 0; r < 4; ++r) {
                            const int rr = half * 4 + r;
                            #pragma unroll
                            for (int q = 0; q < 8; ++q) {
                                ulonglong2 va = *(const ulonglong2*)(inb + rr * LST + q * 4);
                                ffma2(acc0[r], wih0[2*q], va.x); ffma2(acc0[r], wih0[2*q+1], va.y);
                                ffma2(acc1[r], wih1[2*q], va.x); ffma2(acc1[r], wih1[2*q+1], va.y);
                            }
                        }
                    }
                }
                if (l == 0) { xs += 4; if (xs == XDEP) xs = 0; }
            }
            if (l >= 1) nbar(l + 1, up_cnt);
            nbar(l + 2, dn_cnt);
        }
    }
    // =========================== HALF WARP ===========================
    else {
        const int hw = wid - 8;
        const int lh = 8 + (hw >> 1);
        const int rb = (hw & 1) * 4;
        const int r0e = 2 * hw;
        const int r1e = 2 * hw + 1;

        ull wih[16], whh[16];
        {
            const ulonglong2* p;
            p = (const ulonglong2*)(W_ih + (lh * HID + lane) * HID);
            #pragma unroll
            for (int q = 0; q < 8; ++q) { ulonglong2 v = p[q]; wih[2*q] = v.x; wih[2*q+1] = v.y; }
            p = (const ulonglong2*)(W_hh + (lh * HID + lane) * HID);
            #pragma unroll
            for (int q = 0; q < 8; ++q) { ulonglong2 v = p[q]; whh[2*q] = v.x; whh[2*q+1] = v.y; }
        }
        const float bias = __ldg(&b_ih[lh * HID + lane]) + __ldg(&b_hh[lh * HID + lane]);

        for (int i = wid; i < PREF * ROWS; i += 12) {
            const int t = i >> 3, r = i & 7;
            const int idx = __ldg(&x[(row0 + r) * TT + t]);
            sx[t * RL + r * LST + lane] = __ldg(&emb[idx * HID + lane]);
        }
        __syncthreads();

        const float* base_in  = shl + (lh - 1) * DEPTH * RL;
        float*       base_own = shl + lh * DEPTH * RL;

        int4 xiA = *(const int4*)(x + (row0 + r0e) * TT + PREF);
        int4 xiB = *(const int4*)(x + (row0 + r1e) * TT + PREF);
        int ws = PREF;

        ull acc[4];

        for (int v = 0; v < NTICK; ++v) {
            const int te = 4 * v + PREF;
            const bool doemb = (te < TT);
            float g[8];
            if (doemb) {
                g[0] = __ldg(&emb[xiA.x * HID + lane]);
                g[1] = __ldg(&emb[xiA.y * HID + lane]);
                g[2] = __ldg(&emb[xiA.z * HID + lane]);
                g[3] = __ldg(&emb[xiA.w * HID + lane]);
                g[4] = __ldg(&emb[xiB.x * HID + lane]);
                g[5] = __ldg(&emb[xiB.y * HID + lane]);
                g[6] = __ldg(&emb[xiB.z * HID + lane]);
                g[7] = __ldg(&emb[xiB.w * HID + lane]);
                const int tn = te + 4;
                if (tn < TT) {
                    xiA = *(const int4*)(x + (row0 + r0e) * TT + tn);
                    xiB = *(const int4*)(x + (row0 + r1e) * TT + tn);
                }
            }

            const int t0 = 4 * (v - lh);
            if (t0 >= 0 && t0 < TT) {
                {
                    const float* inb = base_in + (t0 & (DEPTH-1)) * RL;
                    #pragma unroll
                    for (int r = 0; r < 4; ++r) acc[r] = 0ull;
                    #pragma unroll
                    for (int r = 0; r < 4; ++r) {
                        const int rr = rb + r;
                        #pragma unroll
                        for (int q = 0; q < 8; ++q) {
                            ulonglong2 va = *(const ulonglong2*)(inb + rr * LST + q * 4);
                            ffma2(acc[r], wih[2*q], va.x); ffma2(acc[r], wih[2*q+1], va.y);
                        }
                    }
                }
                #pragma unroll
                for (int st = 0; st < 4; ++st) {
                    const int t = t0 + st;
                    __syncwarp();
                    const float* hb = base_own + ((t - 1) & (DEPTH-1)) * RL;
                    float*       ob = base_own + (t & (DEPTH-1)) * RL;

                    #pragma unroll
                    for (int r = 0; r < 4; ++r) {
                        const int rr = rb + r;
                        #pragma unroll
                        for (int q = 0; q < 8; ++q) {
                            ulonglong2 vh = *(const ulonglong2*)(hb + rr * LST + q * 4);
                            ffma2(acc[r], whh[2*q], vh.x); ffma2(acc[r], whh[2*q+1], vh.y);
                        }
                    }
                    #pragma unroll
                    for (int r = 0; r < 4; ++r)
                        ob[(rb + r) * LST + lane] = tanh_fast(f2red(acc[r]) + bias);

                    if (st < 3) {
                        const float* inb = base_in + ((t + 1) & (DEPTH-1)) * RL;
                        #pragma unroll
                        for (int r = 0; r < 4; ++r) acc[r] = 0ull;
                        #pragma unroll
                        for (int r = 0; r < 4; ++r) {
                            const int rr = rb + r;
                            #pragma unroll
                            for (int q = 0; q < 8; ++q) {
                                ulonglong2 va = *(const ulonglong2*)(inb + rr * LST + q * 4);
                                ffma2(acc[r], wih[2*q], va.x); ffma2(acc[r], wih[2*q+1], va.y);
                            }
                        }
                    }
                }
            }

            if (doemb) {
                #pragma unroll
                for (int s = 0; s < 4; ++s) {
                    sx[(ws + s) * RL + r0e * LST + lane] = g[s];
                    sx[(ws + s) * RL + r1e * LST + lane] = g[4 + s];
                }
                ws += 4; if (ws == XDEP) ws = 0;
            }

            if (lh == 8) { nbar(9, 96); nbar(10, 128); }
            else         { nbar(10, 128); }
        }
    }

    __syncthreads();

    const float* h9 = shl + ((LL - 1) * DEPTH + 7) * RL;
    for (int i = tid; i < ROWS * VOC; i += NTHR) {
        const int r = i >> 8;
        const int v = i & (VOC - 1);
        const float4* w  = (const float4*)(W_fc + v * HID);
        const float*  hr = h9 + r * LST;
        float sum = __ldg(&b_fc[v]);
        #pragma unroll
        for (int q = 0; q < 8; ++q) {
            float4 a = w[q];
            sum += a.x * hr[q*4+0] + a.y * hr[q*4+1] + a.z * hr[q*4+2] + a.w * hr[q*4+3];
        }
        out[(row0 + r) * VOC + v] = sum;
    }
}

extern "C" void kernel_launch(void* const* d_in, const int* in_sizes, int n_in,
                              void* d_out, int out_size)
{
    const int*   x    = (const int*)  d_in[0];
    const float* emb  = (const float*)d_in[1];
    const float* W_ih = (const float*)d_in[2];
    const float* W_hh = (const float*)d_in[3];
    const float* b_ih = (const float*)d_in[4];
    const float* b_hh = (const float*)d_in[5];
    const float* W_fc = (const float*)d_in[6];
    const float* b_fc = (const float*)d_in[7];
    float* out = (float*)d_out;

    const int shbytes = (LL * DEPTH + XDEP) * RL * (int)sizeof(float);
    cudaFuncSetAttribute(charrnn_kernel,
                         cudaFuncAttributeMaxDynamicSharedMemorySize, shbytes);
    charrnn_kernel<<<NBLK, NTHR, shbytes>>>(x, emb, W_ih, W_hh, b_ih, b_hh,
                                            W_fc, b_fc, out);
}